// round 5
// baseline (speedup 1.0000x reference)
#include <cuda_runtime.h>
#include <cuda_fp16.h>

// Problem constants
#define NW 16384   // words
#define WL 16      // word length
#define D  300     // hidden dim
#define DP 320     // padded channel count for fp16 table
#define NL 128     // letters
#define KS 3       // conv taps

// Encode config: slices of 128/128/44 channels
#define WPB 16
#define ENC_THREADS 512
#define B0 119
#define B1 119
#define B2 59
#define ENC_BLOCKS (B0 + B1 + B2)           // 297
#define ENC_SMEM (KS * NL * 128 * 2)        // 96 KB -> 2 CTA/SM

// Device scratch
__device__ __half g_Ph[KS][NL][DP];  // per-letter conv partials (fp16, padded)
__device__ float  g_embT[D * NL];    // emb transposed: [i][v]
__device__ uint4  g_wpk[NW];         // packed letters: 16 u8 per word

// ---------------------------------------------------------------------------
// Kernel 0: transpose emb [128][300] -> embT [300][128] (tiled, coalesced).
// ---------------------------------------------------------------------------
__global__ __launch_bounds__(256) void transpose_emb_kernel(const float* __restrict__ emb) {
    __shared__ float t[32][33];
    const int i0 = blockIdx.x * 32;   // i tile (10 tiles, last partial)
    const int v0 = blockIdx.y * 32;   // v tile (4 tiles)
    const int x = threadIdx.x, y = threadIdx.y;  // 32 x 8
#pragma unroll
    for (int dy = 0; dy < 32; dy += 8) {
        int v = v0 + y + dy, i = i0 + x;
        t[y + dy][x] = (i < D) ? emb[v * D + i] : 0.f;
    }
    __syncthreads();
#pragma unroll
    for (int dy = 0; dy < 32; dy += 8) {
        int i = i0 + y + dy, v = v0 + x;
        if (i < D) g_embT[i * NL + v] = t[x][y + dy];
    }
}

// ---------------------------------------------------------------------------
// Kernel 1: build P. 320 blocks (one per padded output channel), 128 threads
// (one per letter). w row staged de-interleaved (wk[k][i]); embT reads are
// fully coalesced (lane = v). ~900 FMA/thread, FMA/LSU-bound, ~2 us.
// ---------------------------------------------------------------------------
__global__ __launch_bounds__(128) void compute_P_kernel(const float* __restrict__ w) {
    __shared__ __align__(16) float wk[KS][304];
    const int o = blockIdx.x;
    const int v = threadIdx.x;

    if (o >= D) {  // padded channels: zero fill (uniform per block)
        g_Ph[0][v][o] = __float2half(0.f);
        g_Ph[1][v][o] = __float2half(0.f);
        g_Ph[2][v][o] = __float2half(0.f);
        return;
    }
    for (int t = threadIdx.x; t < D * KS; t += 128)
        wk[t % 3][t / 3] = w[o * D * KS + t];
    __syncthreads();

    const float* et = g_embT + v;  // stride NL
    float a0 = 0.f, a1 = 0.f, a2 = 0.f;
#pragma unroll 5
    for (int i = 0; i < D; i += 4) {
        float4 w0 = *(const float4*)&wk[0][i];
        float4 w1 = *(const float4*)&wk[1][i];
        float4 w2 = *(const float4*)&wk[2][i];
        float e0 = et[(i + 0) * NL];
        float e1 = et[(i + 1) * NL];
        float e2 = et[(i + 2) * NL];
        float e3 = et[(i + 3) * NL];
        a0 = fmaf(e0, w0.x, a0); a1 = fmaf(e0, w1.x, a1); a2 = fmaf(e0, w2.x, a2);
        a0 = fmaf(e1, w0.y, a0); a1 = fmaf(e1, w1.y, a1); a2 = fmaf(e1, w2.y, a2);
        a0 = fmaf(e2, w0.z, a0); a1 = fmaf(e2, w1.z, a1); a2 = fmaf(e2, w2.z, a2);
        a0 = fmaf(e3, w0.w, a0); a1 = fmaf(e3, w1.w, a1); a2 = fmaf(e3, w2.w, a2);
    }
    g_Ph[0][v][o] = __float2half(a0);
    g_Ph[1][v][o] = __float2half(a1);
    g_Ph[2][v][o] = __float2half(a2);
}

// ---------------------------------------------------------------------------
// Kernel 2: pack each word's 16 letters (all < 128) into one uint4 of u8.
// Reads are coalesced per position (consecutive threads -> consecutive n).
// ---------------------------------------------------------------------------
__global__ __launch_bounds__(256) void pack_words_kernel(const int* __restrict__ words) {
    int n = blockIdx.x * blockDim.x + threadIdx.x;
    if (n >= NW) return;
    unsigned r0 = 0, r1 = 0, r2 = 0, r3 = 0;
#pragma unroll
    for (int l = 0; l < 4; ++l)  r0 |= ((unsigned)words[l * NW + n] & 0xFF) << (l * 8);
#pragma unroll
    for (int l = 4; l < 8; ++l)  r1 |= ((unsigned)words[l * NW + n] & 0xFF) << ((l - 4) * 8);
#pragma unroll
    for (int l = 8; l < 12; ++l) r2 |= ((unsigned)words[l * NW + n] & 0xFF) << ((l - 8) * 8);
#pragma unroll
    for (int l = 12; l < 16; ++l) r3 |= ((unsigned)words[l * NW + n] & 0xFF) << ((l - 12) * 8);
    g_wpk[n] = make_uint4(r0, r1, r2, r3);
}

// ---------------------------------------------------------------------------
// Kernel 3: encode. Block stages its fp16 P-slice (96 KB) in smem; each warp
// handles 2 words (half-warp each). Letters arrive as one broadcast LDG.128
// per half-warp, prefetched one iteration ahead. Per position: 3 conflict-free
// LDS.128 + half2 adds + half2 running max. Bias + ReLU in fp32 at the end.
// ---------------------------------------------------------------------------
#define GETL(l) ((lw[(l) >> 2] >> (((l) & 3) * 8)) & 0xFF)

__global__ __launch_bounds__(ENC_THREADS, 2) void encode_kernel(const float* __restrict__ bias,
                                                                float* __restrict__ out) {
    extern __shared__ uint4 Pv[];  // [KS*NL rows][16 uint4]

    int b = blockIdx.x;
    int slice, lb, nb;
    if (b < B0)           { slice = 0; lb = b;           nb = B0; }
    else if (b < B0 + B1) { slice = 1; lb = b - B0;      nb = B1; }
    else                  { slice = 2; lb = b - B0 - B1; nb = B2; }
    const int c0 = slice * 128;
    const int nchunk = (slice == 2) ? 8 : 16;

    const uint4* gP = (const uint4*)g_Ph;  // row stride DP/8 = 40 uint4
    for (int idx = threadIdx.x; idx < KS * NL * nchunk; idx += ENC_THREADS) {
        int r = idx / nchunk, c = idx % nchunk;
        Pv[r * 16 + c] = gP[r * (DP / 8) + slice * 16 + c];
    }
    __syncthreads();

    const int lane  = threadIdx.x & 31;
    const int lo    = lane & 15;
    const int half  = (lane >> 4);  // 0 = word A, 1 = word B
    const int wid   = threadIdx.x >> 5;
    const int wsl   = lb * WPB + wid;
    const int nwarp = nb * WPB;

    const bool active = lo < nchunk;
    const int ch = c0 + lo * 8;

    float4 bb0 = make_float4(0.f, 0.f, 0.f, 0.f);
    float4 bb1 = bb0;
    if (active) {
        if (ch < D)     bb0 = *(const float4*)&bias[ch];
        if (ch + 4 < D) bb1 = *(const float4*)&bias[ch + 4];
    }

    const __half NH = __ushort_as_half((unsigned short)0xFC00);  // -inf
    const half2 NEGI = __halves2half2(NH, NH);

    if (wsl >= NW / 2) return;
    uint4 pk = g_wpk[2 * wsl + half];  // prefetched letters for first word

    for (int p = wsl; p < NW / 2; p += nwarp) {
        // prefetch next iteration's letters
        const int pn = p + nwarp;
        uint4 nxt = make_uint4(0, 0, 0, 0);
        if (pn < NW / 2) nxt = g_wpk[2 * pn + half];

        unsigned lw[4] = {pk.x, pk.y, pk.z, pk.w};
        const int gw = 2 * p + half;

        if (active) {
            half2 m0 = NEGI, m1 = NEGI, m2 = NEGI, m3 = NEGI;
#pragma unroll
            for (int l = 0; l < WL; ++l) {
                uint4 a = Pv[(NL + GETL(l)) * 16 + lo];  // k=1, this char
                half2 h0 = *(half2*)&a.x, h1 = *(half2*)&a.y;
                half2 h2 = *(half2*)&a.z, h3 = *(half2*)&a.w;
                if (l > 0) {
                    uint4 q = Pv[GETL(l - 1) * 16 + lo];  // k=0, prev char
                    h0 = __hadd2(h0, *(half2*)&q.x); h1 = __hadd2(h1, *(half2*)&q.y);
                    h2 = __hadd2(h2, *(half2*)&q.z); h3 = __hadd2(h3, *(half2*)&q.w);
                }
                if (l < WL - 1) {
                    uint4 q = Pv[(2 * NL + GETL(l + 1)) * 16 + lo];  // k=2, next char
                    h0 = __hadd2(h0, *(half2*)&q.x); h1 = __hadd2(h1, *(half2*)&q.y);
                    h2 = __hadd2(h2, *(half2*)&q.z); h3 = __hadd2(h3, *(half2*)&q.w);
                }
                m0 = __hmax2(m0, h0); m1 = __hmax2(m1, h1);
                m2 = __hmax2(m2, h2); m3 = __hmax2(m3, h3);
            }

            float2 f0 = __half22float2(m0), f1 = __half22float2(m1);
            float2 f2 = __half22float2(m2), f3 = __half22float2(m3);
            float* op = out + (size_t)gw * D + ch;
            if (ch < D) {
                float4 r;
                r.x = fmaxf(f0.x + bb0.x, 0.f); r.y = fmaxf(f0.y + bb0.y, 0.f);
                r.z = fmaxf(f1.x + bb0.z, 0.f); r.w = fmaxf(f1.y + bb0.w, 0.f);
                *(float4*)op = r;
            }
            if (ch + 4 < D) {
                float4 r;
                r.x = fmaxf(f2.x + bb1.x, 0.f); r.y = fmaxf(f2.y + bb1.y, 0.f);
                r.z = fmaxf(f3.x + bb1.z, 0.f); r.w = fmaxf(f3.y + bb1.w, 0.f);
                *(float4*)(op + 4) = r;
            }
        }
        pk = nxt;
    }
}

// ---------------------------------------------------------------------------
// Launch. Inputs: words(int32), emb(f32), conv_w(f32), conv_b(f32). Out f32.
// ---------------------------------------------------------------------------
extern "C" void kernel_launch(void* const* d_in, const int* in_sizes, int n_in,
                              void* d_out, int out_size) {
    const int*   words = (const int*)d_in[0];
    const float* emb   = (const float*)d_in[1];
    const float* w     = (const float*)d_in[2];
    const float* b     = (const float*)d_in[3];
    float*       out   = (float*)d_out;

    transpose_emb_kernel<<<dim3(10, 4), dim3(32, 8)>>>(emb);
    pack_words_kernel<<<NW / 256, 256>>>(words);
    compute_P_kernel<<<DP, 128>>>(w);

    cudaFuncSetAttribute(encode_kernel,
                         cudaFuncAttributeMaxDynamicSharedMemorySize, ENC_SMEM);
    encode_kernel<<<ENC_BLOCKS, ENC_THREADS, ENC_SMEM>>>(b, out);
}